// round 1
// baseline (speedup 1.0000x reference)
#include <cuda_runtime.h>
#include <math.h>

// ---------------- problem constants ----------------
#define T_TOK 4096
#define H_DIM 2048
#define E_EXP 32          // routed experts
#define NE    48          // routed + zero experts
#define I_DIM 1024
#define TOPK  6
#define ROUTED_SCALE 2.5f
#define CAP   4096        // per-expert token capacity (worst case = T)

// ---------------- device scratch (static, no allocs) ----------------
__device__ int   g_count[E_EXP];
__device__ int   g_tok[E_EXP * CAP];          // token id per (expert, slot)
__device__ int   g_nk[T_TOK];                 // routed count per token
__device__ int   g_slots[T_TOK * TOPK];       // global slot = e*CAP + pos
__device__ float g_wts[T_TOK * TOPK];
__device__ float g_zero_w[T_TOK];
__device__ float g_act[(size_t)E_EXP * CAP * I_DIM];   // ~512 MB BSS (sparse-touched)
__device__ float g_y[(size_t)E_EXP * CAP * H_DIM];     // ~1 GB BSS (sparse-touched)

// ---------------- kernel 0: zero counters ----------------
__global__ void zero_counts_kernel() {
    int i = threadIdx.x;
    if (i < E_EXP) g_count[i] = 0;
}

// ---------------- kernel 1: router ----------------
__global__ __launch_bounds__(256)
void router_kernel(const float* __restrict__ x,
                   const float* __restrict__ rw,
                   const float* __restrict__ bias) {
    int t   = blockIdx.x;
    int tid = threadIdx.x;
    __shared__ float sx[H_DIM];
    __shared__ float slog[NE];

    const float* xrow = x + (size_t)t * H_DIM;
    for (int i = tid; i < H_DIM; i += 256) sx[i] = xrow[i];
    __syncthreads();

    int warp = tid >> 5, lane = tid & 31;
    for (int e = warp; e < NE; e += 8) {
        const float* w = rw + (size_t)e * H_DIM;
        float acc = 0.f;
        for (int i = lane; i < H_DIM; i += 32) acc += sx[i] * w[i];
        #pragma unroll
        for (int o = 16; o; o >>= 1) acc += __shfl_xor_sync(0xffffffffu, acc, o);
        if (lane == 0) slog[e] = acc;
    }
    __syncthreads();

    if (tid == 0) {
        float sc[NE], scc[NE];
        #pragma unroll
        for (int e = 0; e < NE; e++) {
            float s = 1.f / (1.f + expf(-slog[e]));
            sc[e]  = s;
            scc[e] = s + bias[e];
        }
        int ids[TOPK]; float wts[TOPK]; float sum = 0.f;
        bool used[NE];
        #pragma unroll
        for (int e = 0; e < NE; e++) used[e] = false;
        #pragma unroll
        for (int k = 0; k < TOPK; k++) {
            int bi = 0; float bv = -1e30f;
            for (int e = 0; e < NE; e++) {
                if (!used[e] && scc[e] > bv) { bv = scc[e]; bi = e; }  // strict > : lowest idx on tie (jax)
            }
            used[bi] = true; ids[k] = bi; wts[k] = sc[bi]; sum += sc[bi];
        }
        float inv = ROUTED_SCALE / sum;
        float zw = 0.f;
        int nk = 0;
        #pragma unroll
        for (int k = 0; k < TOPK; k++) {
            float w = wts[k] * inv;
            if (ids[k] >= E_EXP) {
                zw += w;
            } else {
                int e = ids[k];
                int pos = atomicAdd(&g_count[e], 1);
                g_tok[e * CAP + pos] = t;
                g_slots[t * TOPK + nk] = e * CAP + pos;
                g_wts[t * TOPK + nk] = w;
                nk++;
            }
        }
        g_nk[t] = nk;
        g_zero_w[t] = zw;
    }
}

// ---------------- GEMM tiling ----------------
#define BM 64
#define BN 64
#define BK 16

// kernel 2: act = silu(x@w1^T) * (x@w3^T), grouped by expert (gathered rows)
__global__ __launch_bounds__(256, 2)
void gemm1_kernel(const float* __restrict__ x,
                  const float* __restrict__ w1,
                  const float* __restrict__ w3) {
    int e   = blockIdx.z;
    int cnt = g_count[e];
    int m0  = blockIdx.y * BM;
    if (m0 >= cnt) return;
    int n0  = blockIdx.x * BN;

    __shared__ float As[BK][BM + 4];
    __shared__ float B1[BK][BN + 4];
    __shared__ float B3[BK][BN + 4];

    int tid  = threadIdx.x;
    int lrow = tid >> 2;           // 0..63
    int lc4  = (tid & 3) * 4;      // 0,4,8,12

    int  arow   = m0 + lrow;
    bool avalid = arow < cnt;
    int  tok    = avalid ? g_tok[e * CAP + arow] : 0;
    const float* xrow  = x  + (size_t)tok * H_DIM;
    const float* b1row = w1 + ((size_t)e * I_DIM + n0 + lrow) * H_DIM;
    const float* b3row = w3 + ((size_t)e * I_DIM + n0 + lrow) * H_DIM;

    float4 fa, f1, f3;
    fa = avalid ? *(const float4*)(xrow + lc4) : make_float4(0.f, 0.f, 0.f, 0.f);
    f1 = *(const float4*)(b1row + lc4);
    f3 = *(const float4*)(b3row + lc4);

    float accg[4][4] = {}, accu[4][4] = {};
    int ty = tid >> 4, tx = tid & 15;
    int msub = ty * 4, nsub = tx * 4;

    const int nkt = H_DIM / BK;
    for (int kt = 0; kt < nkt; kt++) {
        As[lc4 + 0][lrow] = fa.x; As[lc4 + 1][lrow] = fa.y;
        As[lc4 + 2][lrow] = fa.z; As[lc4 + 3][lrow] = fa.w;
        B1[lc4 + 0][lrow] = f1.x; B1[lc4 + 1][lrow] = f1.y;
        B1[lc4 + 2][lrow] = f1.z; B1[lc4 + 3][lrow] = f1.w;
        B3[lc4 + 0][lrow] = f3.x; B3[lc4 + 1][lrow] = f3.y;
        B3[lc4 + 2][lrow] = f3.z; B3[lc4 + 3][lrow] = f3.w;
        __syncthreads();

        if (kt + 1 < nkt) {
            int k0 = (kt + 1) * BK;
            fa = avalid ? *(const float4*)(xrow + k0 + lc4) : make_float4(0.f, 0.f, 0.f, 0.f);
            f1 = *(const float4*)(b1row + k0 + lc4);
            f3 = *(const float4*)(b3row + k0 + lc4);
        }

        #pragma unroll
        for (int kk = 0; kk < BK; kk++) {
            float4 av  = *(const float4*)&As[kk][msub];
            float4 g4  = *(const float4*)&B1[kk][nsub];
            float4 u4  = *(const float4*)&B3[kk][nsub];
            float am[4] = {av.x, av.y, av.z, av.w};
            float gn[4] = {g4.x, g4.y, g4.z, g4.w};
            float un[4] = {u4.x, u4.y, u4.z, u4.w};
            #pragma unroll
            for (int mi = 0; mi < 4; mi++)
                #pragma unroll
                for (int ni = 0; ni < 4; ni++) {
                    accg[mi][ni] += am[mi] * gn[ni];
                    accu[mi][ni] += am[mi] * un[ni];
                }
        }
        __syncthreads();
    }

    #pragma unroll
    for (int mi = 0; mi < 4; mi++) {
        int row = m0 + msub + mi;
        if (row < cnt) {
            float v[4];
            #pragma unroll
            for (int ni = 0; ni < 4; ni++) {
                float g = accg[mi][ni], u = accu[mi][ni];
                float s = g / (1.f + expf(-g));   // silu
                v[ni] = s * u;
            }
            float* dst = &g_act[((size_t)e * CAP + row) * I_DIM + n0 + nsub];
            *(float4*)dst = make_float4(v[0], v[1], v[2], v[3]);
        }
    }
}

// kernel 3: y = act @ w2^T per expert, write to per-slot buffer (deterministic)
__global__ __launch_bounds__(256, 2)
void gemm2_kernel(const float* __restrict__ w2) {
    int e   = blockIdx.z;
    int cnt = g_count[e];
    int m0  = blockIdx.y * BM;
    if (m0 >= cnt) return;
    int n0  = blockIdx.x * BN;

    __shared__ float As[BK][BM + 4];
    __shared__ float Bs[BK][BN + 4];

    int tid  = threadIdx.x;
    int lrow = tid >> 2;
    int lc4  = (tid & 3) * 4;

    int  arow   = m0 + lrow;
    bool avalid = arow < cnt;
    const float* aptr = g_act + ((size_t)e * CAP + (avalid ? arow : 0)) * I_DIM;
    const float* brow = w2 + ((size_t)e * H_DIM + n0 + lrow) * I_DIM;

    float4 fa, fb;
    fa = avalid ? *(const float4*)(aptr + lc4) : make_float4(0.f, 0.f, 0.f, 0.f);
    fb = *(const float4*)(brow + lc4);

    float acc[4][4] = {};
    int ty = tid >> 4, tx = tid & 15;
    int msub = ty * 4, nsub = tx * 4;

    const int nkt = I_DIM / BK;
    for (int kt = 0; kt < nkt; kt++) {
        As[lc4 + 0][lrow] = fa.x; As[lc4 + 1][lrow] = fa.y;
        As[lc4 + 2][lrow] = fa.z; As[lc4 + 3][lrow] = fa.w;
        Bs[lc4 + 0][lrow] = fb.x; Bs[lc4 + 1][lrow] = fb.y;
        Bs[lc4 + 2][lrow] = fb.z; Bs[lc4 + 3][lrow] = fb.w;
        __syncthreads();

        if (kt + 1 < nkt) {
            int k0 = (kt + 1) * BK;
            fa = avalid ? *(const float4*)(aptr + k0 + lc4) : make_float4(0.f, 0.f, 0.f, 0.f);
            fb = *(const float4*)(brow + k0 + lc4);
        }

        #pragma unroll
        for (int kk = 0; kk < BK; kk++) {
            float4 av = *(const float4*)&As[kk][msub];
            float4 bv = *(const float4*)&Bs[kk][nsub];
            float am[4] = {av.x, av.y, av.z, av.w};
            float bn[4] = {bv.x, bv.y, bv.z, bv.w};
            #pragma unroll
            for (int mi = 0; mi < 4; mi++)
                #pragma unroll
                for (int ni = 0; ni < 4; ni++)
                    acc[mi][ni] += am[mi] * bn[ni];
        }
        __syncthreads();
    }

    #pragma unroll
    for (int mi = 0; mi < 4; mi++) {
        int row = m0 + msub + mi;
        if (row < cnt) {
            float* dst = &g_y[((size_t)e * CAP + row) * H_DIM + n0 + nsub];
            *(float4*)dst = make_float4(acc[mi][0], acc[mi][1], acc[mi][2], acc[mi][3]);
        }
    }
}

// kernel 4: out[t] = x[t]*zero_w + sum_k w_k * y[slot_k]
__global__ __launch_bounds__(256)
void combine_kernel(const float* __restrict__ x, float* __restrict__ out) {
    int t = blockIdx.x;
    __shared__ int   s_n;
    __shared__ float s_zw;
    __shared__ int   s_slot[TOPK];
    __shared__ float s_w[TOPK];
    int tid = threadIdx.x;
    if (tid == 0) { s_n = g_nk[t]; s_zw = g_zero_w[t]; }
    if (tid < TOPK) { s_slot[tid] = g_slots[t * TOPK + tid]; s_w[tid] = g_wts[t * TOPK + tid]; }
    __syncthreads();
    int n = s_n; float zw = s_zw;

    const float* xrow = x + (size_t)t * H_DIM;
    float* orow = out + (size_t)t * H_DIM;
    for (int h = tid * 4; h < H_DIM; h += 256 * 4) {
        float4 xv = *(const float4*)(xrow + h);
        float4 o = make_float4(xv.x * zw, xv.y * zw, xv.z * zw, xv.w * zw);
        for (int k = 0; k < n; k++) {
            const float4 yv = *(const float4*)(g_y + (size_t)s_slot[k] * H_DIM + h);
            float w = s_w[k];
            o.x += w * yv.x; o.y += w * yv.y; o.z += w * yv.z; o.w += w * yv.w;
        }
        *(float4*)(orow + h) = o;
    }
}

// ---------------- launcher ----------------
extern "C" void kernel_launch(void* const* d_in, const int* in_sizes, int n_in,
                              void* d_out, int out_size) {
    const float* x    = (const float*)d_in[0];   // [T, H]
    const float* rw   = (const float*)d_in[1];   // [E+Z, H]
    const float* bias = (const float*)d_in[2];   // [E+Z]
    const float* w1   = (const float*)d_in[3];   // [E, I, H]
    const float* w3   = (const float*)d_in[4];   // [E, I, H]
    const float* w2   = (const float*)d_in[5];   // [E, H, I]
    float* out = (float*)d_out;                   // [T, H]

    zero_counts_kernel<<<1, 32>>>();
    router_kernel<<<T_TOK, 256>>>(x, rw, bias);
    {
        dim3 g(I_DIM / BN, T_TOK / BM, E_EXP);   // 16 x 64 x 32, most exit early
        gemm1_kernel<<<g, 256>>>(x, w1, w3);
    }
    {
        dim3 g(H_DIM / BN, T_TOK / BM, E_EXP);   // 32 x 64 x 32
        gemm2_kernel<<<g, 256>>>(w2);
    }
    combine_kernel<<<T_TOK, 256>>>(x, out);
}

// round 3
// speedup vs baseline: 2.0359x; 2.0359x over previous
#include <cuda_runtime.h>
#include <math.h>
#include <stdint.h>

// ---------------- problem constants ----------------
#define T_TOK 4096
#define H_DIM 2048
#define E_EXP 32          // routed experts
#define NE    48          // routed + zero experts
#define I_DIM 1024
#define TOPK  6
#define ROUTED_SCALE 2.5f
#define CAP   4096        // per-expert token capacity (worst case = T)

// ---------------- device scratch (static, no allocs) ----------------
__device__ int   g_count[E_EXP];
__device__ int   g_tok[E_EXP * CAP];          // token id per (expert, slot)
__device__ int   g_nk[T_TOK];                 // routed count per token
__device__ int   g_slots[T_TOK * TOPK];       // global slot = e*CAP + pos
__device__ float g_wts[T_TOK * TOPK];
__device__ float g_zero_w[T_TOK];
__device__ float g_act[(size_t)E_EXP * CAP * I_DIM];   // sparse-touched
__device__ float g_y[(size_t)E_EXP * CAP * H_DIM];     // sparse-touched

// ---------------- kernel 0: zero counters ----------------
__global__ void zero_counts_kernel() {
    int i = threadIdx.x;
    if (i < E_EXP) g_count[i] = 0;
}

// ---------------- kernel 1: router (exact fp32 — selection must not flip) ----------------
__global__ __launch_bounds__(256)
void router_kernel(const float* __restrict__ x,
                   const float* __restrict__ rw,
                   const float* __restrict__ bias) {
    int t   = blockIdx.x;
    int tid = threadIdx.x;
    __shared__ float sx[H_DIM];
    __shared__ float slog[NE];

    const float* xrow = x + (size_t)t * H_DIM;
    for (int i = tid; i < H_DIM; i += 256) sx[i] = xrow[i];
    __syncthreads();

    int warp = tid >> 5, lane = tid & 31;
    for (int e = warp; e < NE; e += 8) {
        const float* w = rw + (size_t)e * H_DIM;
        float acc = 0.f;
        for (int i = lane; i < H_DIM; i += 32) acc += sx[i] * w[i];
        #pragma unroll
        for (int o = 16; o; o >>= 1) acc += __shfl_xor_sync(0xffffffffu, acc, o);
        if (lane == 0) slog[e] = acc;
    }
    __syncthreads();

    if (tid == 0) {
        float sc[NE], scc[NE];
        #pragma unroll
        for (int e = 0; e < NE; e++) {
            float s = 1.f / (1.f + expf(-slog[e]));
            sc[e]  = s;
            scc[e] = s + bias[e];
        }
        int ids[TOPK]; float wts[TOPK]; float sum = 0.f;
        bool used[NE];
        #pragma unroll
        for (int e = 0; e < NE; e++) used[e] = false;
        #pragma unroll
        for (int k = 0; k < TOPK; k++) {
            int bi = 0; float bv = -1e30f;
            for (int e = 0; e < NE; e++) {
                if (!used[e] && scc[e] > bv) { bv = scc[e]; bi = e; }  // strict > : lowest idx on tie
            }
            used[bi] = true; ids[k] = bi; wts[k] = sc[bi]; sum += sc[bi];
        }
        float inv = ROUTED_SCALE / sum;
        float zw = 0.f;
        int nk = 0;
        #pragma unroll
        for (int k = 0; k < TOPK; k++) {
            float w = wts[k] * inv;
            if (ids[k] >= E_EXP) {
                zw += w;
            } else {
                int e = ids[k];
                int pos = atomicAdd(&g_count[e], 1);
                g_tok[e * CAP + pos] = t;
                g_slots[t * TOPK + nk] = e * CAP + pos;
                g_wts[t * TOPK + nk] = w;
                nk++;
            }
        }
        g_nk[t] = nk;
        g_zero_w[t] = zw;
    }
}

// ---------------- tensor-core helpers ----------------
__device__ __forceinline__ uint32_t f2tf(float f) {
    uint32_t r;
    asm("cvt.rna.tf32.f32 %0, %1;" : "=r"(r) : "f"(f));
    return r;
}

__device__ __forceinline__ void mma_tf32(float* d,
                                         const uint32_t* a,
                                         const uint32_t* b) {
    asm volatile(
        "mma.sync.aligned.m16n8k8.row.col.f32.tf32.tf32.f32 "
        "{%0,%1,%2,%3}, {%4,%5,%6,%7}, {%8,%9}, {%0,%1,%2,%3};\n"
        : "+f"(d[0]), "+f"(d[1]), "+f"(d[2]), "+f"(d[3])
        : "r"(a[0]), "r"(a[1]), "r"(a[2]), "r"(a[3]),
          "r"(b[0]), "r"(b[1]));
}

// ---------------- GEMM tiling ----------------
#define BM 128
#define BK 32
#define SPAD 36   // smem row stride (floats): %32==4 -> conflict-free frag loads

// kernel 2: act = silu(x@w1^T) * (x@w3^T), grouped by expert (gathered rows).
// B tile = 64 interleaved rows: row 2j = w1[f0+j], row 2j+1 = w3[f0+j].
// => thread accumulator pair (d0,d1)/(d2,d3) is (gate, up) of one feature.
__global__ __launch_bounds__(256)
void gemm1_kernel(const float* __restrict__ x,
                  const float* __restrict__ w1,
                  const float* __restrict__ w3) {
    int e   = blockIdx.z;
    int cnt = g_count[e];
    int m0  = blockIdx.y * BM;
    if (m0 >= cnt) return;
    int fbase = blockIdx.x * 32;      // 32 features per block (64 interleaved B rows)

    __shared__ uint32_t As[BM][SPAD];
    __shared__ uint32_t Bs[64][SPAD];

    int tid  = threadIdx.x;
    int warp = tid >> 5, lane = tid & 31;
    int wm = warp >> 1, wn = warp & 1;          // 4x2 warp grid, warp tile 32x32
    int g  = lane >> 2, tg = lane & 3;

    // ---- loader assignment ----
    // A: row = tid>>1 (0..127), 16 consecutive floats at col (tid&1)*16
    int ar = tid >> 1;
    int ac = (tid & 1) * 16;
    bool av = (m0 + ar) < cnt;
    int tok = av ? g_tok[e * CAP + m0 + ar] : 0;
    const float* aptr = x + (size_t)tok * H_DIM + ac;
    // B: row = tid>>2 (0..63), 8 floats at col (tid&3)*8
    int br = tid >> 2;
    int bc = (tid & 3) * 8;
    const float* bsrc = ((br & 1) ? w3 : w1)
                      + ((size_t)e * I_DIM + fbase + (br >> 1)) * H_DIM + bc;

    float4 ra[4], rb[2];
    #pragma unroll
    for (int i = 0; i < 4; i++)
        ra[i] = av ? *(const float4*)(aptr + i * 4) : make_float4(0.f, 0.f, 0.f, 0.f);
    #pragma unroll
    for (int i = 0; i < 2; i++)
        rb[i] = *(const float4*)(bsrc + i * 4);

    float acc[2][4][4];
    #pragma unroll
    for (int mt = 0; mt < 2; mt++)
        #pragma unroll
        for (int nt = 0; nt < 4; nt++)
            #pragma unroll
            for (int i = 0; i < 4; i++) acc[mt][nt][i] = 0.f;

    const int nkt = H_DIM / BK;
    for (int kt = 0; kt < nkt; kt++) {
        // regs -> smem (converted to tf32)
        #pragma unroll
        for (int i = 0; i < 4; i++) {
            As[ar][ac + i*4 + 0] = f2tf(ra[i].x);
            As[ar][ac + i*4 + 1] = f2tf(ra[i].y);
            As[ar][ac + i*4 + 2] = f2tf(ra[i].z);
            As[ar][ac + i*4 + 3] = f2tf(ra[i].w);
        }
        #pragma unroll
        for (int i = 0; i < 2; i++) {
            Bs[br][bc + i*4 + 0] = f2tf(rb[i].x);
            Bs[br][bc + i*4 + 1] = f2tf(rb[i].y);
            Bs[br][bc + i*4 + 2] = f2tf(rb[i].z);
            Bs[br][bc + i*4 + 3] = f2tf(rb[i].w);
        }
        __syncthreads();

        if (kt + 1 < nkt) {
            int k0 = (kt + 1) * BK;
            #pragma unroll
            for (int i = 0; i < 4; i++)
                ra[i] = av ? *(const float4*)(aptr + k0 + i * 4)
                           : make_float4(0.f, 0.f, 0.f, 0.f);
            #pragma unroll
            for (int i = 0; i < 2; i++)
                rb[i] = *(const float4*)(bsrc + k0 + i * 4);
        }

        #pragma unroll
        for (int kk = 0; kk < BK / 8; kk++) {
            int k8 = kk * 8;
            uint32_t afr[2][4], bfr[4][2];
            #pragma unroll
            for (int mt = 0; mt < 2; mt++) {
                int rb0 = wm * 32 + mt * 16;
                afr[mt][0] = As[rb0 + g     ][k8 + tg    ];
                afr[mt][1] = As[rb0 + g + 8 ][k8 + tg    ];
                afr[mt][2] = As[rb0 + g     ][k8 + tg + 4];
                afr[mt][3] = As[rb0 + g + 8 ][k8 + tg + 4];
            }
            #pragma unroll
            for (int nt = 0; nt < 4; nt++) {
                int nb = wn * 32 + nt * 8;
                bfr[nt][0] = Bs[nb + g][k8 + tg    ];
                bfr[nt][1] = Bs[nb + g][k8 + tg + 4];
            }
            #pragma unroll
            for (int mt = 0; mt < 2; mt++)
                #pragma unroll
                for (int nt = 0; nt < 4; nt++)
                    mma_tf32(acc[mt][nt], afr[mt], bfr[nt]);
        }
        __syncthreads();
    }

    // epilogue: silu(gate)*up per accumulator pair
    #pragma unroll
    for (int mt = 0; mt < 2; mt++) {
        int row0 = m0 + wm * 32 + mt * 16 + g;
        #pragma unroll
        for (int nt = 0; nt < 4; nt++) {
            int f = fbase + wn * 16 + nt * 4 + tg;
            float* acc4 = acc[mt][nt];
            if (row0 < cnt) {
                float gt = acc4[0], up = acc4[1];
                g_act[((size_t)e * CAP + row0) * I_DIM + f] = (gt / (1.f + expf(-gt))) * up;
            }
            if (row0 + 8 < cnt) {
                float gt = acc4[2], up = acc4[3];
                g_act[((size_t)e * CAP + row0 + 8) * I_DIM + f] = (gt / (1.f + expf(-gt))) * up;
            }
        }
    }
}

// kernel 3: y = act @ w2^T per expert, per-slot output (deterministic)
__global__ __launch_bounds__(256)
void gemm2_kernel(const float* __restrict__ w2) {
    int e   = blockIdx.z;
    int cnt = g_count[e];
    int m0  = blockIdx.y * BM;
    if (m0 >= cnt) return;
    int n0  = blockIdx.x * 64;

    __shared__ uint32_t As[BM][SPAD];
    __shared__ uint32_t Bs[64][SPAD];

    int tid  = threadIdx.x;
    int warp = tid >> 5, lane = tid & 31;
    int wm = warp >> 1, wn = warp & 1;
    int g  = lane >> 2, tg = lane & 3;

    int ar = tid >> 1;
    int ac = (tid & 1) * 16;
    bool av = (m0 + ar) < cnt;
    const float* aptr = g_act + ((size_t)e * CAP + (av ? (m0 + ar) : 0)) * I_DIM + ac;
    int br = tid >> 2;
    int bc = (tid & 3) * 8;
    const float* bsrc = w2 + ((size_t)e * H_DIM + n0 + br) * I_DIM + bc;

    float4 ra[4], rb[2];
    #pragma unroll
    for (int i = 0; i < 4; i++)
        ra[i] = av ? *(const float4*)(aptr + i * 4) : make_float4(0.f, 0.f, 0.f, 0.f);
    #pragma unroll
    for (int i = 0; i < 2; i++)
        rb[i] = *(const float4*)(bsrc + i * 4);

    float acc[2][4][4];
    #pragma unroll
    for (int mt = 0; mt < 2; mt++)
        #pragma unroll
        for (int nt = 0; nt < 4; nt++)
            #pragma unroll
            for (int i = 0; i < 4; i++) acc[mt][nt][i] = 0.f;

    const int nkt = I_DIM / BK;
    for (int kt = 0; kt < nkt; kt++) {
        #pragma unroll
        for (int i = 0; i < 4; i++) {
            As[ar][ac + i*4 + 0] = f2tf(ra[i].x);
            As[ar][ac + i*4 + 1] = f2tf(ra[i].y);
            As[ar][ac + i*4 + 2] = f2tf(ra[i].z);
            As[ar][ac + i*4 + 3] = f2tf(ra[i].w);
        }
        #pragma unroll
        for (int i = 0; i < 2; i++) {
            Bs[br][bc + i*4 + 0] = f2tf(rb[i].x);
            Bs[br][bc + i*4 + 1] = f2tf(rb[i].y);
            Bs[br][bc + i*4 + 2] = f2tf(rb[i].z);
            Bs[br][bc + i*4 + 3] = f2tf(rb[i].w);
        }
        __syncthreads();

        if (kt + 1 < nkt) {
            int k0 = (kt + 1) * BK;
            #pragma unroll
            for (int i = 0; i < 4; i++)
                ra[i] = av ? *(const float4*)(aptr + k0 + i * 4)
                           : make_float4(0.f, 0.f, 0.f, 0.f);
            #pragma unroll
            for (int i = 0; i < 2; i++)
                rb[i] = *(const float4*)(bsrc + k0 + i * 4);
        }

        #pragma unroll
        for (int kk = 0; kk < BK / 8; kk++) {
            int k8 = kk * 8;
            uint32_t afr[2][4], bfr[4][2];
            #pragma unroll
            for (int mt = 0; mt < 2; mt++) {
                int rb0 = wm * 32 + mt * 16;
                afr[mt][0] = As[rb0 + g     ][k8 + tg    ];
                afr[mt][1] = As[rb0 + g + 8 ][k8 + tg    ];
                afr[mt][2] = As[rb0 + g     ][k8 + tg + 4];
                afr[mt][3] = As[rb0 + g + 8 ][k8 + tg + 4];
            }
            #pragma unroll
            for (int nt = 0; nt < 4; nt++) {
                int nb = wn * 32 + nt * 8;
                bfr[nt][0] = Bs[nb + g][k8 + tg    ];
                bfr[nt][1] = Bs[nb + g][k8 + tg + 4];
            }
            #pragma unroll
            for (int mt = 0; mt < 2; mt++)
                #pragma unroll
                for (int nt = 0; nt < 4; nt++)
                    mma_tf32(acc[mt][nt], afr[mt], bfr[nt]);
        }
        __syncthreads();
    }

    // epilogue: d0,d1 at (row, col 2tg / 2tg+1) -> float2 stores
    #pragma unroll
    for (int mt = 0; mt < 2; mt++) {
        int row0 = m0 + wm * 32 + mt * 16 + g;
        #pragma unroll
        for (int nt = 0; nt < 4; nt++) {
            int col = n0 + wn * 32 + nt * 8 + 2 * tg;
            float* acc4 = acc[mt][nt];
            if (row0 < cnt)
                *(float2*)&g_y[((size_t)e * CAP + row0) * H_DIM + col]
                    = make_float2(acc4[0], acc4[1]);
            if (row0 + 8 < cnt)
                *(float2*)&g_y[((size_t)e * CAP + row0 + 8) * H_DIM + col]
                    = make_float2(acc4[2], acc4[3]);
        }
    }
}

// kernel 4: out[t] = x[t]*zero_w + sum_k w_k * y[slot_k]
__global__ __launch_bounds__(256)
void combine_kernel(const float* __restrict__ x, float* __restrict__ out) {
    int t = blockIdx.x;
    __shared__ int   s_n;
    __shared__ float s_zw;
    __shared__ int   s_slot[TOPK];
    __shared__ float s_w[TOPK];
    int tid = threadIdx.x;
    if (tid == 0) { s_n = g_nk[t]; s_zw = g_zero_w[t]; }
    if (tid < TOPK) { s_slot[tid] = g_slots[t * TOPK + tid]; s_w[tid] = g_wts[t * TOPK + tid]; }
    __syncthreads();
    int n = s_n; float zw = s_zw;

    const float* xrow = x + (size_t)t * H_DIM;
    float* orow = out + (size_t)t * H_DIM;
    for (int h = tid * 4; h < H_DIM; h += 256 * 4) {
        float4 xv = *(const float4*)(xrow + h);
        float4 o = make_float4(xv.x * zw, xv.y * zw, xv.z * zw, xv.w * zw);
        for (int k = 0; k < n; k++) {
            const float4 yv = *(const float4*)(g_y + (size_t)s_slot[k] * H_DIM + h);
            float w = s_w[k];
            o.x += w * yv.x; o.y += w * yv.y; o.z += w * yv.z; o.w += w * yv.w;
        }
        *(float4*)(orow + h) = o;
    }
}

// ---------------- launcher ----------------
extern "C" void kernel_launch(void* const* d_in, const int* in_sizes, int n_in,
                              void* d_out, int out_size) {
    const float* x    = (const float*)d_in[0];   // [T, H]
    const float* rw   = (const float*)d_in[1];   // [E+Z, H]
    const float* bias = (const float*)d_in[2];   // [E+Z]
    const float* w1   = (const float*)d_in[3];   // [E, I, H]
    const float* w3   = (const float*)d_in[4];   // [E, I, H]
    const float* w2   = (const float*)d_in[5];   // [E, H, I]
    float* out = (float*)d_out;                   // [T, H]

    zero_counts_kernel<<<1, 32>>>();
    router_kernel<<<T_TOK, 256>>>(x, rw, bias);
    {
        dim3 g(I_DIM / 32, T_TOK / BM, E_EXP);   // 32 x 32 x 32, most exit early
        gemm1_kernel<<<g, 256>>>(x, w1, w3);
    }
    {
        dim3 g(H_DIM / 64, T_TOK / BM, E_EXP);   // 32 x 32 x 32
        gemm2_kernel<<<g, 256>>>(w2);
    }
    combine_kernel<<<T_TOK, 256>>>(x, out);
}